// round 1
// baseline (speedup 1.0000x reference)
#include <cuda_runtime.h>
#include <cuda_bf16.h>
#include <cstdint>

// Problem shape (fixed by setup_inputs): B=2,H=16,S=2048,D=64, fp32.
// Output tuple packed as [context (B*H*S*D) | attn (B*H*S*S)] fp32.
#define BB 2
#define HH 16
#define SS 2048
#define DD 64
#define NEG_BIG (-1e9f)
#define SCALE 0.125f  // 1/sqrt(64)

// Mask dtype flag, resolved at runtime by a probe kernel:
// 0 = int32 {0,1}, 1 = float32 {0.0,1.0}, 2 = uint8 {0,1}
__device__ int g_mask_flag;

__global__ void probe_mask_kernel(const void* m) {
    if (threadIdx.x == 0 && blockIdx.x == 0) {
        const unsigned int* w = (const unsigned int*)m;
        bool all01 = true, allf = true;
        for (int i = 0; i < 1024; i++) {
            unsigned int v = w[i];
            if (v != 0u && v != 1u) all01 = false;
            if (v != 0u && v != 0x3F800000u) allf = false;
        }
        // uint8-packed random 0/1 bytes cannot produce 1024 words all in {0,1}
        // nor all in {0, 0x3F800000}; so those patterns identify i32 / f32.
        g_mask_flag = all01 ? 0 : (allf ? 1 : 2);
    }
}

__device__ __forceinline__ bool mask_at(const void* m, size_t idx, int flag) {
    if (flag == 2) return ((const unsigned char*)m)[idx] != 0;
    if (flag == 1) return ((const float*)m)[idx] != 0.0f;
    return ((const int*)m)[idx] != 0;
}

// ---------------------------------------------------------------------------
// Kernel 1: scores = Q @ K^T * scale, masked -> written raw into attn region.
// Block tile: 128 q-rows x 64 k-cols. 256 threads, 8x4 register tile each.
// Smem stored transposed ([d][row]) so inner loop uses 3x LDS.128 per d-step.
// ---------------------------------------------------------------------------
__global__ __launch_bounds__(256) void qk_kernel(
    const float* __restrict__ Q, const float* __restrict__ K,
    const void* __restrict__ mask, float* __restrict__ attn)
{
    __shared__ float QsT[DD][128 + 4];  // [d][q-row]
    __shared__ float KsT[DD][64 + 4];   // [d][k-row]

    const int bh = blockIdx.z;
    const int b  = bh >> 4;
    const int q0 = blockIdx.y * 128;
    const int k0 = blockIdx.x * 64;

    const float* Qp = Q + ((size_t)bh * SS + q0) * DD;
    const float* Kp = K + ((size_t)bh * SS + k0) * DD;

    const int tid = threadIdx.x;
    for (int i = tid; i < 128 * DD; i += 256) {
        int r = i >> 6, c = i & 63;
        QsT[c][r] = Qp[i];
    }
    for (int i = tid; i < 64 * DD; i += 256) {
        int r = i >> 6, c = i & 63;
        KsT[c][r] = Kp[i];
    }
    __syncthreads();

    const int ty = tid >> 4, tx = tid & 15;
    const int r0 = ty * 8, c0 = tx * 4;

    float acc[8][4];
#pragma unroll
    for (int i = 0; i < 8; i++)
#pragma unroll
        for (int j = 0; j < 4; j++) acc[i][j] = 0.0f;

#pragma unroll 4
    for (int d = 0; d < DD; d++) {
        float4 a0 = *(const float4*)&QsT[d][r0];
        float4 a1 = *(const float4*)&QsT[d][r0 + 4];
        float4 bv = *(const float4*)&KsT[d][c0];
        float a[8] = {a0.x, a0.y, a0.z, a0.w, a1.x, a1.y, a1.z, a1.w};
        float bb[4] = {bv.x, bv.y, bv.z, bv.w};
#pragma unroll
        for (int i = 0; i < 8; i++)
#pragma unroll
            for (int j = 0; j < 4; j++) acc[i][j] = fmaf(a[i], bb[j], acc[i][j]);
    }

    const int flag = g_mask_flag;
#pragma unroll
    for (int i = 0; i < 8; i++) {
        int q = q0 + r0 + i;
        size_t orow = ((size_t)bh * SS + q) * SS + (size_t)(k0 + c0);
        size_t mrow = ((size_t)b * SS + q) * SS + (size_t)(k0 + c0);
        float4 w;
        w.x = mask_at(mask, mrow + 0, flag) ? NEG_BIG : acc[i][0] * SCALE;
        w.y = mask_at(mask, mrow + 1, flag) ? NEG_BIG : acc[i][1] * SCALE;
        w.z = mask_at(mask, mrow + 2, flag) ? NEG_BIG : acc[i][2] * SCALE;
        w.w = mask_at(mask, mrow + 3, flag) ? NEG_BIG : acc[i][3] * SCALE;
        *(float4*)&attn[orow] = w;
    }
}

// ---------------------------------------------------------------------------
// Kernel 2: row softmax in place. One block (256 threads) per (b,h,q) row.
// ---------------------------------------------------------------------------
__global__ __launch_bounds__(256) void softmax_kernel(float* __restrict__ attn)
{
    __shared__ float red[8];
    const size_t row = blockIdx.x;
    float* p = attn + row * (size_t)SS;
    const int tid = threadIdx.x;
    const int lane = tid & 31, wid = tid >> 5;

    float4 x0 = *(const float4*)&p[tid * 8];
    float4 x1 = *(const float4*)&p[tid * 8 + 4];
    float v[8] = {x0.x, x0.y, x0.z, x0.w, x1.x, x1.y, x1.z, x1.w};

    float m = -1e30f;
#pragma unroll
    for (int i = 0; i < 8; i++) m = fmaxf(m, v[i]);
#pragma unroll
    for (int o = 16; o > 0; o >>= 1) m = fmaxf(m, __shfl_xor_sync(0xffffffffu, m, o));
    if (lane == 0) red[wid] = m;
    __syncthreads();
#pragma unroll
    for (int j = 0; j < 8; j++) m = fmaxf(m, red[j]);

    float e[8];
    float s = 0.0f;
#pragma unroll
    for (int i = 0; i < 8; i++) { e[i] = __expf(v[i] - m); s += e[i]; }
#pragma unroll
    for (int o = 16; o > 0; o >>= 1) s += __shfl_xor_sync(0xffffffffu, s, o);
    __syncthreads();  // all reads of red (max phase) done
    if (lane == 0) red[wid] = s;
    __syncthreads();
    float tot = 0.0f;
#pragma unroll
    for (int j = 0; j < 8; j++) tot += red[j];
    float inv = 1.0f / tot;

    float4 y0, y1;
    y0.x = e[0] * inv; y0.y = e[1] * inv; y0.z = e[2] * inv; y0.w = e[3] * inv;
    y1.x = e[4] * inv; y1.y = e[5] * inv; y1.z = e[6] * inv; y1.w = e[7] * inv;
    *(float4*)&p[tid * 8]     = y0;
    *(float4*)&p[tid * 8 + 4] = y1;
}

// ---------------------------------------------------------------------------
// Kernel 3: context = attn @ V. Block tile: 128 q-rows x 64 (full D) cols,
// k-loop in chunks of 64. Same 8x4 register tiling.
// ---------------------------------------------------------------------------
__global__ __launch_bounds__(256) void pv_kernel(
    const float* __restrict__ attn, const float* __restrict__ V,
    float* __restrict__ ctx)
{
    __shared__ float AsT[64][128 + 4];  // [kk][q-row]
    __shared__ float Vs[64][64 + 4];    // [kk][d]

    const int bh = blockIdx.z;
    const int q0 = blockIdx.y * 128;
    const float* Ap = attn + ((size_t)bh * SS + q0) * SS;
    const float* Vp = V + (size_t)bh * SS * DD;

    const int tid = threadIdx.x;
    const int ty = tid >> 4, tx = tid & 15;
    const int r0 = ty * 8, c0 = tx * 4;

    float acc[8][4];
#pragma unroll
    for (int i = 0; i < 8; i++)
#pragma unroll
        for (int j = 0; j < 4; j++) acc[i][j] = 0.0f;

    for (int k0 = 0; k0 < SS; k0 += 64) {
        for (int i = tid; i < 128 * 64; i += 256) {
            int r = i >> 6, kk = i & 63;
            AsT[kk][r] = Ap[(size_t)r * SS + k0 + kk];
        }
        for (int i = tid; i < 64 * 64; i += 256) {
            int kk = i >> 6, c = i & 63;
            Vs[kk][c] = Vp[(size_t)(k0 + kk) * DD + c];
        }
        __syncthreads();

#pragma unroll 4
        for (int kk = 0; kk < 64; kk++) {
            float4 a0 = *(const float4*)&AsT[kk][r0];
            float4 a1 = *(const float4*)&AsT[kk][r0 + 4];
            float4 bv = *(const float4*)&Vs[kk][c0];
            float a[8] = {a0.x, a0.y, a0.z, a0.w, a1.x, a1.y, a1.z, a1.w};
            float bb[4] = {bv.x, bv.y, bv.z, bv.w};
#pragma unroll
            for (int i = 0; i < 8; i++)
#pragma unroll
                for (int j = 0; j < 4; j++) acc[i][j] = fmaf(a[i], bb[j], acc[i][j]);
        }
        __syncthreads();
    }

#pragma unroll
    for (int i = 0; i < 8; i++) {
        size_t o = ((size_t)bh * SS + q0 + r0 + i) * DD + c0;
        float4 w;
        w.x = acc[i][0]; w.y = acc[i][1]; w.z = acc[i][2]; w.w = acc[i][3];
        *(float4*)&ctx[o] = w;
    }
}

// ---------------------------------------------------------------------------
extern "C" void kernel_launch(void* const* d_in, const int* in_sizes, int n_in,
                              void* d_out, int out_size)
{
    const float* Q = (const float*)d_in[0];
    const float* K = (const float*)d_in[1];
    const float* V = (const float*)d_in[2];
    const void*  M = d_in[3];

    float* out  = (float*)d_out;
    float* ctx  = out;                                   // B*H*S*D elements
    float* attn = out + (size_t)BB * HH * SS * DD;       // B*H*S*S elements

    probe_mask_kernel<<<1, 32>>>(M);

    dim3 g1(SS / 64, SS / 128, BB * HH);
    qk_kernel<<<g1, 256>>>(Q, K, M, attn);

    softmax_kernel<<<(unsigned)((size_t)BB * HH * SS), 256>>>(attn);

    dim3 g3(1, SS / 128, BB * HH);
    pv_kernel<<<g3, 256>>>(attn, V, ctx);
}

// round 3
// speedup vs baseline: 1.1829x; 1.1829x over previous
#include <cuda_runtime.h>
#include <cuda_bf16.h>
#include <cstdint>

#define BB 2
#define HH 16
#define SS 2048
#define DD 64
#define NEG_BIG (-1e9f)
#define SCALE 0.125f

// ---------------------------------------------------------------------------
// mask dtype probe: 0 = int32 {0,1}, 1 = float32 {0,1.0f}, 2 = uint8 {0,1}
// ---------------------------------------------------------------------------
__device__ int g_mask_flag;

__global__ void probe_mask_kernel(const void* m) {
    if (threadIdx.x == 0 && blockIdx.x == 0) {
        const unsigned int* w = (const unsigned int*)m;
        bool all01 = true, allf = true;
        for (int i = 0; i < 1024; i++) {
            unsigned int v = w[i];
            if (v != 0u && v != 1u) all01 = false;
            if (v != 0u && v != 0x3F800000u) allf = false;
        }
        g_mask_flag = all01 ? 0 : (allf ? 1 : 2);
    }
}

__device__ __forceinline__ bool mask_at(const void* m, size_t idx, int flag) {
    if (flag == 2) return ((const unsigned char*)m)[idx] != 0;
    if (flag == 1) return ((const float*)m)[idx] != 0.0f;
    return ((const int*)m)[idx] != 0;
}

// ---------------------------------------------------------------------------
// warp-MMA helpers (sm_80-era PTX: compiles on plain compute_103)
// ---------------------------------------------------------------------------
__device__ __forceinline__ uint32_t smem_u32(const void* p) {
    uint32_t a;
    asm("{ .reg .u64 t; cvta.to.shared.u64 t, %1; cvt.u32.u64 %0, t; }"
        : "=r"(a) : "l"(p));
    return a;
}

__device__ __forceinline__ void ldsm4(uint32_t* r, uint32_t addr) {
    asm volatile("ldmatrix.sync.aligned.m8n8.x4.shared.b16 {%0,%1,%2,%3}, [%4];"
                 : "=r"(r[0]), "=r"(r[1]), "=r"(r[2]), "=r"(r[3]) : "r"(addr));
}

__device__ __forceinline__ void mma_bf16(float* c, const uint32_t* a,
                                         const uint32_t b0, const uint32_t b1) {
    asm volatile(
        "mma.sync.aligned.m16n8k16.row.col.f32.bf16.bf16.f32 "
        "{%0,%1,%2,%3}, {%4,%5,%6,%7}, {%8,%9}, {%0,%1,%2,%3};"
        : "+f"(c[0]), "+f"(c[1]), "+f"(c[2]), "+f"(c[3])
        : "r"(a[0]), "r"(a[1]), "r"(a[2]), "r"(a[3]), "r"(b0), "r"(b1));
}

#define PAD 72   // bf16 row stride (144B): conflict-free ldmatrix

// ---------------------------------------------------------------------------
// QK kernel: raw masked scores -> attn region. CTA tile 128q x 128k.
// 8 warps as 4(m) x 2(n); warp tile 32m x 64n. bf16 hi/lo 3-term split.
// smem: Qh,Ql,Kh,Kl each [128][72] bf16 = 73728 B (reused as epi staging).
// ---------------------------------------------------------------------------
__global__ __launch_bounds__(256) void qk_mma_kernel(
    const float* __restrict__ Q, const float* __restrict__ K,
    const void* __restrict__ mask, float* __restrict__ attn)
{
    extern __shared__ __align__(16) char smem[];
    __nv_bfloat16* Qh = (__nv_bfloat16*)smem;
    __nv_bfloat16* Ql = Qh + 128 * PAD;
    __nv_bfloat16* Kh = Ql + 128 * PAD;
    __nv_bfloat16* Kl = Kh + 128 * PAD;
    float* sbuf = (float*)smem;   // epilogue: [128][129]

    const int tid = threadIdx.x, lane = tid & 31, wid = tid >> 5;
    const int bh = blockIdx.z, b = bh >> 4;
    const int q0 = blockIdx.y * 128, k0 = blockIdx.x * 128;

    const float* Qp = Q + ((size_t)bh * SS + q0) * DD;
    const float* Kp = K + ((size_t)bh * SS + k0) * DD;

    for (int i = tid; i < 128 * 64; i += 256) {
        int r = i >> 6, c = i & 63;
        float q = Qp[i];
        __nv_bfloat16 qh = __float2bfloat16(q);
        Qh[r * PAD + c] = qh;
        Ql[r * PAD + c] = __float2bfloat16(q - __bfloat162float(qh));
        float k = Kp[i];
        __nv_bfloat16 kh = __float2bfloat16(k);
        Kh[r * PAD + c] = kh;
        Kl[r * PAD + c] = __float2bfloat16(k - __bfloat162float(kh));
    }
    __syncthreads();

    const int wm = wid >> 1, wn = wid & 1;
    const int m0 = wm * 32, n0 = wn * 64;

    float acc[2][8][4];
#pragma unroll
    for (int i = 0; i < 2; i++)
#pragma unroll
        for (int j = 0; j < 8; j++)
#pragma unroll
            for (int v = 0; v < 4; v++) acc[i][j][v] = 0.0f;

    uint32_t aU[3], bU[3];
    aU[0] = smem_u32(Qh); aU[1] = smem_u32(Qh); aU[2] = smem_u32(Ql);
    bU[0] = smem_u32(Kh); bU[1] = smem_u32(Kl); bU[2] = smem_u32(Kh);

    const int arow = lane & 15, acol8 = (lane >> 4) * 8;

#pragma unroll
    for (int t = 0; t < 3; t++) {
#pragma unroll
        for (int ks = 0; ks < 4; ks++) {
            const int k = ks * 16;
            uint32_t a[2][4];
#pragma unroll
            for (int i = 0; i < 2; i++)
                ldsm4(a[i], aU[t] + (uint32_t)(((m0 + i * 16 + arow) * PAD
                                                + k + acol8) * 2));
            uint32_t bfr[8][2];
#pragma unroll
            for (int jj = 0; jj < 4; jj++) {
                uint32_t bt[4];
                ldsm4(bt, bU[t] + (uint32_t)(((n0 + jj * 16 + arow) * PAD
                                              + k + acol8) * 2));
                bfr[2 * jj][0] = bt[0]; bfr[2 * jj][1] = bt[2];
                bfr[2 * jj + 1][0] = bt[1]; bfr[2 * jj + 1][1] = bt[3];
            }
#pragma unroll
            for (int i = 0; i < 2; i++)
#pragma unroll
                for (int j = 0; j < 8; j++)
                    mma_bf16(acc[i][j], a[i], bfr[j][0], bfr[j][1]);
        }
    }
    __syncthreads();

    // stage accumulators -> smem (float [128][129])
#pragma unroll
    for (int i = 0; i < 2; i++)
#pragma unroll
        for (int j = 0; j < 8; j++) {
            int row = m0 + i * 16 + (lane >> 2);
            int col = n0 + j * 8 + (lane & 3) * 2;
            sbuf[row * 129 + col]           = acc[i][j][0];
            sbuf[row * 129 + col + 1]       = acc[i][j][1];
            sbuf[(row + 8) * 129 + col]     = acc[i][j][2];
            sbuf[(row + 8) * 129 + col + 1] = acc[i][j][3];
        }
    __syncthreads();

    const int flag = g_mask_flag;
    for (int i = tid; i < 128 * 128; i += 256) {
        int r = i >> 7, c = i & 127;
        size_t arowo = ((size_t)bh * SS + q0 + r) * SS + (size_t)(k0 + c);
        size_t mrow  = ((size_t)b  * SS + q0 + r) * SS + (size_t)(k0 + c);
        float v = sbuf[r * 129 + c] * SCALE;
        attn[arowo] = mask_at(mask, mrow, flag) ? NEG_BIG : v;
    }
}

// ---------------------------------------------------------------------------
// Softmax: in-place per row. One block (256 threads) per (b,h,q).
// ---------------------------------------------------------------------------
__global__ __launch_bounds__(256) void softmax_kernel(float* __restrict__ attn)
{
    __shared__ float red[8];
    const size_t row = blockIdx.x;
    float* p = attn + row * (size_t)SS;
    const int tid = threadIdx.x;
    const int lane = tid & 31, wid = tid >> 5;

    float4 x0 = *(const float4*)&p[tid * 8];
    float4 x1 = *(const float4*)&p[tid * 8 + 4];
    float v[8] = {x0.x, x0.y, x0.z, x0.w, x1.x, x1.y, x1.z, x1.w};

    float m = -1e30f;
#pragma unroll
    for (int i = 0; i < 8; i++) m = fmaxf(m, v[i]);
#pragma unroll
    for (int o = 16; o > 0; o >>= 1) m = fmaxf(m, __shfl_xor_sync(0xffffffffu, m, o));
    if (lane == 0) red[wid] = m;
    __syncthreads();
#pragma unroll
    for (int j = 0; j < 8; j++) m = fmaxf(m, red[j]);

    float e[8];
    float s = 0.0f;
#pragma unroll
    for (int i = 0; i < 8; i++) { e[i] = __expf(v[i] - m); s += e[i]; }
#pragma unroll
    for (int o = 16; o > 0; o >>= 1) s += __shfl_xor_sync(0xffffffffu, s, o);
    __syncthreads();
    if (lane == 0) red[wid] = s;
    __syncthreads();
    float tot = 0.0f;
#pragma unroll
    for (int j = 0; j < 8; j++) tot += red[j];
    float inv = 1.0f / tot;

    float4 y0, y1;
    y0.x = e[0] * inv; y0.y = e[1] * inv; y0.z = e[2] * inv; y0.w = e[3] * inv;
    y1.x = e[4] * inv; y1.y = e[5] * inv; y1.z = e[6] * inv; y1.w = e[7] * inv;
    *(float4*)&p[tid * 8]     = y0;
    *(float4*)&p[tid * 8 + 4] = y1;
}

// ---------------------------------------------------------------------------
// PV kernel: ctx = attn @ V. CTA 128m x 64n; k-chunks of 64 over SS.
// 8 warps as 4(m) x 2(n); warp tile 32m x 32n. bf16 hi/lo 3-term split.
// smem: Ph,Pl [128][72], Vh,Vl [64][72] bf16 = 55296 B (reused as staging).
// ---------------------------------------------------------------------------
__global__ __launch_bounds__(256) void pv_mma_kernel(
    const float* __restrict__ attn, const float* __restrict__ V,
    float* __restrict__ ctx)
{
    extern __shared__ __align__(16) char smem[];
    __nv_bfloat16* Ph = (__nv_bfloat16*)smem;
    __nv_bfloat16* Pl = Ph + 128 * PAD;
    __nv_bfloat16* Vh = Pl + 128 * PAD;
    __nv_bfloat16* Vl = Vh + 64 * PAD;
    float* sbuf = (float*)smem;   // epilogue: [128][65]

    const int tid = threadIdx.x, lane = tid & 31, wid = tid >> 5;
    const int bh = blockIdx.z;
    const int q0 = blockIdx.y * 128;

    const float* Ap = attn + ((size_t)bh * SS + q0) * SS;
    const float* Vp = V + (size_t)bh * SS * DD;

    const int wm = wid >> 1, wn = wid & 1;
    const int m0 = wm * 32, n0 = wn * 32;

    float acc[2][4][4];
#pragma unroll
    for (int i = 0; i < 2; i++)
#pragma unroll
        for (int j = 0; j < 4; j++)
#pragma unroll
            for (int v = 0; v < 4; v++) acc[i][j][v] = 0.0f;

    uint32_t aU[3], bU[3];
    aU[0] = smem_u32(Ph); aU[1] = smem_u32(Ph); aU[2] = smem_u32(Pl);
    bU[0] = smem_u32(Vh); bU[1] = smem_u32(Vl); bU[2] = smem_u32(Vh);

    const int arow = lane & 15, acol8 = (lane >> 4) * 8;

    for (int kc = 0; kc < 32; kc++) {
        for (int i = tid; i < 128 * 64; i += 256) {
            int r = i >> 6, c = i & 63;
            float pv = Ap[(size_t)r * SS + (size_t)(kc * 64 + c)];
            __nv_bfloat16 ph = __float2bfloat16(pv);
            Ph[r * PAD + c] = ph;
            Pl[r * PAD + c] = __float2bfloat16(pv - __bfloat162float(ph));
        }
        for (int i = tid; i < 64 * 64; i += 256) {
            int kk = i >> 6, n = i & 63;
            float vv = Vp[(size_t)(kc * 64 + kk) * DD + n];
            __nv_bfloat16 vh = __float2bfloat16(vv);
            Vh[n * PAD + kk] = vh;                 // transposed: B[n][k]
            Vl[n * PAD + kk] = __float2bfloat16(vv - __bfloat162float(vh));
        }
        __syncthreads();

#pragma unroll
        for (int t = 0; t < 3; t++) {
#pragma unroll
            for (int ks = 0; ks < 4; ks++) {
                const int k = ks * 16;
                uint32_t a[2][4];
#pragma unroll
                for (int i = 0; i < 2; i++)
                    ldsm4(a[i], aU[t] + (uint32_t)(((m0 + i * 16 + arow) * PAD
                                                    + k + acol8) * 2));
                uint32_t bfr[4][2];
#pragma unroll
                for (int jj = 0; jj < 2; jj++) {
                    uint32_t bt[4];
                    ldsm4(bt, bU[t] + (uint32_t)(((n0 + jj * 16 + arow) * PAD
                                                  + k + acol8) * 2));
                    bfr[2 * jj][0] = bt[0]; bfr[2 * jj][1] = bt[2];
                    bfr[2 * jj + 1][0] = bt[1]; bfr[2 * jj + 1][1] = bt[3];
                }
#pragma unroll
                for (int i = 0; i < 2; i++)
#pragma unroll
                    for (int j = 0; j < 4; j++)
                        mma_bf16(acc[i][j], a[i], bfr[j][0], bfr[j][1]);
            }
        }
        __syncthreads();
    }

    // stage -> smem (float [128][65]) -> coalesced write
#pragma unroll
    for (int i = 0; i < 2; i++)
#pragma unroll
        for (int j = 0; j < 4; j++) {
            int row = m0 + i * 16 + (lane >> 2);
            int col = n0 + j * 8 + (lane & 3) * 2;
            sbuf[row * 65 + col]           = acc[i][j][0];
            sbuf[row * 65 + col + 1]       = acc[i][j][1];
            sbuf[(row + 8) * 65 + col]     = acc[i][j][2];
            sbuf[(row + 8) * 65 + col + 1] = acc[i][j][3];
        }
    __syncthreads();

    for (int i = tid; i < 128 * 64; i += 256) {
        int r = i >> 6, c = i & 63;
        ctx[((size_t)bh * SS + q0 + r) * DD + c] = sbuf[r * 65 + c];
    }
}

// ---------------------------------------------------------------------------
extern "C" void kernel_launch(void* const* d_in, const int* in_sizes, int n_in,
                              void* d_out, int out_size)
{
    const float* Q = (const float*)d_in[0];
    const float* K = (const float*)d_in[1];
    const float* V = (const float*)d_in[2];
    const void*  M = d_in[3];

    float* out  = (float*)d_out;
    float* ctx  = out;                                // B*H*S*D
    float* attn = out + (size_t)BB * HH * SS * DD;    // B*H*S*S

    const int QK_SMEM = 4 * 128 * PAD * 2;            // 73728
    const int PV_SMEM = (2 * 128 + 2 * 64) * PAD * 2; // 55296

    cudaFuncSetAttribute(qk_mma_kernel,
                         cudaFuncAttributeMaxDynamicSharedMemorySize, QK_SMEM);
    cudaFuncSetAttribute(pv_mma_kernel,
                         cudaFuncAttributeMaxDynamicSharedMemorySize, PV_SMEM);

    probe_mask_kernel<<<1, 32>>>(M);

    dim3 g1(SS / 128, SS / 128, BB * HH);
    qk_mma_kernel<<<g1, 256, QK_SMEM>>>(Q, K, M, attn);

    softmax_kernel<<<(unsigned)((size_t)BB * HH * SS), 256>>>(attn);

    dim3 g3(1, SS / 128, BB * HH);
    pv_mma_kernel<<<g3, 256, PV_SMEM>>>(attn, V, ctx);
}